// round 1
// baseline (speedup 1.0000x reference)
#include <cuda_runtime.h>

#define NN 50000
#define NE 800000
#define D  128
#define DE 64

typedef unsigned long long ull;

// ---------------- device scratch (no allocs allowed) ----------------
__device__ __align__(16) int   g_deg [NN];
__device__ __align__(16) float g_norm[NN];
__device__ __align__(16) float g_h   [NN * D];   // h = nfeat@Wn + bn
__device__ __align__(16) float g_g   [NN * D];   // norm[n] * h[n]
__device__ __align__(16) float g_aggg[NN * D];   // sum_{e->n} g[src]
__device__ __align__(16) float g_agge[NN * DE];  // sum_{e->n} norm[src]*efeat
__device__ __align__(16) float g_se  [NN];       // sum_{e->n} norm[src]

// ---------------- small PTX helpers ----------------
__device__ __forceinline__ void fma2(ull &d, ull a, ull b) {
    asm("fma.rn.f32x2 %0, %1, %2, %0;" : "+l"(d) : "l"(a), "l"(b));
}
__device__ __forceinline__ ull dup2(float x) {
    ull r; asm("mov.b64 %0, {%1, %1};" : "=l"(r) : "f"(x)); return r;
}
__device__ __forceinline__ ull pack2(float a, float b) {
    ull r; asm("mov.b64 %0, {%1, %2};" : "=l"(r) : "f"(a), "f"(b)); return r;
}
__device__ __forceinline__ float2 unpk(ull v) {
    float2 r; asm("mov.b64 {%0, %1}, %2;" : "=f"(r.x), "=f"(r.y) : "l"(v)); return r;
}
__device__ __forceinline__ void red4(float* p, float4 v) {
    asm volatile("red.global.add.v4.f32 [%0], {%1, %2, %3, %4};"
                 :: "l"(p), "f"(v.x), "f"(v.y), "f"(v.z), "f"(v.w) : "memory");
}

// ---------------- K0: zero scratch ----------------
__global__ void k_zero() {
    int i = blockIdx.x * blockDim.x + threadIdx.x;
    int st = gridDim.x * blockDim.x;
    float4 z = make_float4(0.f, 0.f, 0.f, 0.f);
    for (int j = i; j < NN * D / 4;  j += st) ((float4*)g_aggg)[j] = z;
    for (int j = i; j < NN * DE / 4; j += st) ((float4*)g_agge)[j] = z;
    for (int j = i; j < NN; j += st) { g_se[j] = 0.f; g_deg[j] = 0; }
}

// ---------------- K1: in-degree ----------------
__global__ void k_deg(const int* __restrict__ dst) {
    int i = blockIdx.x * blockDim.x + threadIdx.x;
    if (i < NE) atomicAdd(&g_deg[dst[i]], 1);
}

// ---------------- K2: node GEMM h = nfeat@Wn + bn ; g, norm, out-init ----------------
// 256 threads, tile = 32 nodes, warp w owns nodes 4w..4w+3, lane tx owns dims 4tx..4tx+3.
// Wn staged packed (u64 = 2 dims), nfeat staged duplicated (u64 = {v,v}) -> f32x2 FMAs.
__global__ __launch_bounds__(256) void k_node(
    const float* __restrict__ nfeat, const float* __restrict__ Wn,
    const float* __restrict__ bn, const float* __restrict__ resid,
    float* __restrict__ out)
{
    extern __shared__ ull sm[];
    ull* sW  = sm;            // [128][64] u64 = 64 KB
    ull* sNf = sm + 128 * 64; // [128][32] u64 = 32 KB

    int t = threadIdx.x, lane = t & 31, w = t >> 5;

    // load Wn packed (natural u64 reinterpret)
    const ull* Wn64 = (const ull*)Wn;
    for (int i = t; i < 128 * 64; i += 256) sW[i] = Wn64[i];

    float4 bnv = *(const float4*)&bn[4 * lane];
    ull b01 = pack2(bnv.x, bnv.y), b23 = pack2(bnv.z, bnv.w);
    float4 r4 = *(const float4*)&resid[4 * lane];

    const int NT = (NN + 31) / 32;
    for (int tile = blockIdx.x; tile < NT; tile += gridDim.x) {
        __syncthreads();
        int nt = tile * 32;
        int nl = nt + lane;
        #pragma unroll
        for (int i = 0; i < 4; i++) {
            int k0 = 16 * w + 4 * i;
            float4 v = make_float4(0.f, 0.f, 0.f, 0.f);
            if (nl < NN) v = *(const float4*)&nfeat[(size_t)nl * D + k0];
            sNf[(k0 + 0) * 32 + lane] = dup2(v.x);
            sNf[(k0 + 1) * 32 + lane] = dup2(v.y);
            sNf[(k0 + 2) * 32 + lane] = dup2(v.z);
            sNf[(k0 + 3) * 32 + lane] = dup2(v.w);
        }
        __syncthreads();

        ull acc[4][2];
        #pragma unroll
        for (int j = 0; j < 4; j++) { acc[j][0] = b01; acc[j][1] = b23; }

        #pragma unroll 8
        for (int k = 0; k < 128; k++) {
            ulonglong2 wv  = *(const ulonglong2*)&sW[k * 64 + 2 * lane];
            ulonglong2 n01 = *(const ulonglong2*)&sNf[k * 32 + 4 * w];
            ulonglong2 n23 = *(const ulonglong2*)&sNf[k * 32 + 4 * w + 2];
            fma2(acc[0][0], n01.x, wv.x); fma2(acc[0][1], n01.x, wv.y);
            fma2(acc[1][0], n01.y, wv.x); fma2(acc[1][1], n01.y, wv.y);
            fma2(acc[2][0], n23.x, wv.x); fma2(acc[2][1], n23.x, wv.y);
            fma2(acc[3][0], n23.y, wv.x); fma2(acc[3][1], n23.y, wv.y);
        }

        #pragma unroll
        for (int j = 0; j < 4; j++) {
            int n = nt + 4 * w + j;
            if (n >= NN) continue;
            float dv  = (float)g_deg[n] + 1.0f;
            float inv = 1.0f / dv;
            float nr  = rsqrtf(dv);
            float2 p0 = unpk(acc[j][0]), p1 = unpk(acc[j][1]);
            float4 h4 = make_float4(p0.x, p0.y, p1.x, p1.y);
            *(float4*)&g_h[(size_t)n * D + 4 * lane] = h4;
            *(float4*)&g_g[(size_t)n * D + 4 * lane] =
                make_float4(nr * h4.x, nr * h4.y, nr * h4.z, nr * h4.w);
            *(float4*)&out[(size_t)n * D + 4 * lane] =
                make_float4((h4.x + r4.x) * inv, (h4.y + r4.y) * inv,
                            (h4.z + r4.z) * inv, (h4.w + r4.w) * inv);
            if (lane == 0) g_norm[n] = nr;
        }
    }
}

// ---------------- K3: edge pass (warp per edge, vector RED scatter) ----------------
__global__ __launch_bounds__(256) void k_edge(
    const int* __restrict__ src, const int* __restrict__ dst,
    const float* __restrict__ efeat)
{
    int lane = threadIdx.x & 31;
    int warp = (blockIdx.x * blockDim.x + threadIdx.x) >> 5;
    int nw   = (gridDim.x * blockDim.x) >> 5;
    for (int e = warp; e < NE; e += nw) {
        int s  = src[e];
        int d2 = dst[e];
        float ns = g_norm[s];
        float4 gv = *(const float4*)&g_g[(size_t)s * D + 4 * lane];
        red4(&g_aggg[(size_t)d2 * D + 4 * lane], gv);
        if (lane < 16) {
            float4 ev = *(const float4*)&efeat[(size_t)e * DE + 4 * lane];
            red4(&g_agge[(size_t)d2 * DE + 4 * lane],
                 make_float4(ns * ev.x, ns * ev.y, ns * ev.z, ns * ev.w));
        } else if (lane == 16) {
            atomicAdd(&g_se[d2], ns);
        }
    }
}

// ---------------- K4: out += norm * (aggg + agge@We + se*be) ----------------
__global__ __launch_bounds__(256) void k_out(
    const float* __restrict__ We, const float* __restrict__ be,
    float* __restrict__ out)
{
    extern __shared__ ull sm[];
    ull* sW  = sm;           // [64][64] u64 = 32 KB (We packed)
    ull* sAe = sm + 64 * 64; // [64][32] u64 = 16 KB (agge duplicated)

    int t = threadIdx.x, lane = t & 31, w = t >> 5;

    const ull* We64 = (const ull*)We;
    for (int i = t; i < 64 * 64; i += 256) sW[i] = We64[i];

    float4 be4 = *(const float4*)&be[4 * lane];

    const int NT = (NN + 31) / 32;
    for (int tile = blockIdx.x; tile < NT; tile += gridDim.x) {
        __syncthreads();
        int nt = tile * 32;
        int nl = nt + lane;
        #pragma unroll
        for (int i = 0; i < 2; i++) {
            int k0 = 8 * w + 4 * i;
            float4 v = make_float4(0.f, 0.f, 0.f, 0.f);
            if (nl < NN) v = *(const float4*)&g_agge[(size_t)nl * DE + k0];
            sAe[(k0 + 0) * 32 + lane] = dup2(v.x);
            sAe[(k0 + 1) * 32 + lane] = dup2(v.y);
            sAe[(k0 + 2) * 32 + lane] = dup2(v.z);
            sAe[(k0 + 3) * 32 + lane] = dup2(v.w);
        }
        __syncthreads();

        ull acc[4][2];
        #pragma unroll
        for (int j = 0; j < 4; j++) { acc[j][0] = 0ULL; acc[j][1] = 0ULL; }

        #pragma unroll 8
        for (int k = 0; k < 64; k++) {
            ulonglong2 wv  = *(const ulonglong2*)&sW[k * 64 + 2 * lane];
            ulonglong2 a01 = *(const ulonglong2*)&sAe[k * 32 + 4 * w];
            ulonglong2 a23 = *(const ulonglong2*)&sAe[k * 32 + 4 * w + 2];
            fma2(acc[0][0], a01.x, wv.x); fma2(acc[0][1], a01.x, wv.y);
            fma2(acc[1][0], a01.y, wv.x); fma2(acc[1][1], a01.y, wv.y);
            fma2(acc[2][0], a23.x, wv.x); fma2(acc[2][1], a23.x, wv.y);
            fma2(acc[3][0], a23.y, wv.x); fma2(acc[3][1], a23.y, wv.y);
        }

        #pragma unroll
        for (int j = 0; j < 4; j++) {
            int n = nt + 4 * w + j;
            if (n >= NN) continue;
            float nr = g_norm[n];
            float se = g_se[n];
            float4 ag = *(const float4*)&g_aggg[(size_t)n * D + 4 * lane];
            float4 ov = *(const float4*)&out[(size_t)n * D + 4 * lane];
            float2 p0 = unpk(acc[j][0]), p1 = unpk(acc[j][1]);
            ov.x += nr * (ag.x + p0.x + se * be4.x);
            ov.y += nr * (ag.y + p0.y + se * be4.y);
            ov.z += nr * (ag.z + p1.x + se * be4.z);
            ov.w += nr * (ag.w + p1.y + se * be4.w);
            *(float4*)&out[(size_t)n * D + 4 * lane] = ov;
        }
    }
}

// ---------------- launch ----------------
extern "C" void kernel_launch(void* const* d_in, const int* in_sizes, int n_in,
                              void* d_out, int out_size)
{
    const int*   src   = (const int*)  d_in[0];
    const int*   dst   = (const int*)  d_in[1];
    const float* nfeat = (const float*)d_in[2];
    const float* efeat = (const float*)d_in[3];
    const float* Wn    = (const float*)d_in[4];
    const float* bn    = (const float*)d_in[5];
    const float* We    = (const float*)d_in[6];
    const float* be    = (const float*)d_in[7];
    const float* resid = (const float*)d_in[8];
    float* out = (float*)d_out;

    const int SM_NODE = (128 * 64 + 128 * 32) * 8;  // 96 KB
    const int SM_OUT  = (64 * 64 + 64 * 32) * 8;    // 48 KB
    cudaFuncSetAttribute(k_node, cudaFuncAttributeMaxDynamicSharedMemorySize, SM_NODE);
    cudaFuncSetAttribute(k_out,  cudaFuncAttributeMaxDynamicSharedMemorySize, SM_OUT);

    k_zero<<<912, 256>>>();
    k_deg <<<(NE + 255) / 256, 256>>>(dst);
    k_node<<<296, 256, SM_NODE>>>(nfeat, Wn, bn, resid, out);
    k_edge<<<2368, 256>>>(src, dst, efeat);
    k_out <<<592, 256, SM_OUT>>>(We, be, out);
}

// round 2
// speedup vs baseline: 1.2475x; 1.2475x over previous
#include <cuda_runtime.h>

#define NN 50000
#define NE 800000
#define D  128
#define DE 64
#define CAP 80

typedef unsigned long long ull;

// ---------------- device scratch (no allocs allowed) ----------------
__device__ __align__(16) int   g_deg [NN];
__device__ __align__(16) float g_norm[NN];
__device__ __align__(16) float g_g   [NN * D];     // norm[n] * (nfeat@Wn + bn)
__device__ __align__(16) int2  g_perm[NN * CAP];   // per-dst edge list {src, e}
__device__ __align__(16) int4  g_ovf [1024];       // overflow {src, e, dst, 0}
__device__ int g_novf;

// ---------------- PTX helpers ----------------
__device__ __forceinline__ void fma2(ull &d, ull a, ull b) {
    asm("fma.rn.f32x2 %0, %1, %2, %0;" : "+l"(d) : "l"(a), "l"(b));
}
__device__ __forceinline__ void add2(ull &d, ull a) {
    asm("add.rn.f32x2 %0, %0, %1;" : "+l"(d) : "l"(a));
}
__device__ __forceinline__ ull dup2(float x) {
    ull r; asm("mov.b64 %0, {%1, %1};" : "=l"(r) : "f"(x)); return r;
}
__device__ __forceinline__ ull pack2(float a, float b) {
    ull r; asm("mov.b64 %0, {%1, %2};" : "=l"(r) : "f"(a), "f"(b)); return r;
}
__device__ __forceinline__ float2 unpk(ull v) {
    float2 r; asm("mov.b64 {%0, %1}, %2;" : "=f"(r.x), "=f"(r.y) : "l"(v)); return r;
}
__device__ __forceinline__ void red4(float* p, float4 v) {
    asm volatile("red.global.add.v4.f32 [%0], {%1, %2, %3, %4};"
                 :: "l"(p), "f"(v.x), "f"(v.y), "f"(v.z), "f"(v.w) : "memory");
}

// ---------------- K0: zero counters ----------------
__global__ void k_zero() {
    int i = blockIdx.x * blockDim.x + threadIdx.x;
    int st = gridDim.x * blockDim.x;
    for (int j = i; j < NN; j += st) g_deg[j] = 0;
    if (i == 0) g_novf = 0;
}

// ---------------- K1: build per-dst buckets + degree ----------------
__global__ void k_build(const int* __restrict__ src, const int* __restrict__ dst) {
    int e = blockIdx.x * blockDim.x + threadIdx.x;
    if (e >= NE) return;
    int d = dst[e], s = src[e];
    int c = atomicAdd(&g_deg[d], 1);
    if (c < CAP) {
        g_perm[d * CAP + c] = make_int2(s, e);
    } else {
        int o = atomicAdd(&g_novf, 1);
        if (o < 1024) g_ovf[o] = make_int4(s, e, d, 0);
    }
}

// ---------------- K2: node GEMM  g = norm*(nfeat@Wn+bn);  out = (h+resid)/deg ----------------
__global__ __launch_bounds__(256) void k_node(
    const float* __restrict__ nfeat, const float* __restrict__ Wn,
    const float* __restrict__ bn, const float* __restrict__ resid,
    float* __restrict__ out)
{
    extern __shared__ ull smn[];
    ull*   sW  = smn;                       // [128][64] u64 (Wn dim-pairs) = 64 KB
    float* sNf = (float*)(smn + 128 * 64);  // [k][node] = 32 KB

    int t = threadIdx.x, lane = t & 31, w = t >> 5;

    const ulonglong2* Wn128 = (const ulonglong2*)Wn;
    ulonglong2* sW2 = (ulonglong2*)sW;
    for (int i = t; i < 128 * 64 / 2; i += 256) sW2[i] = Wn128[i];

    float4 bnv = *(const float4*)&bn[4 * lane];
    ull b01 = pack2(bnv.x, bnv.y), b23 = pack2(bnv.z, bnv.w);
    float4 r4 = *(const float4*)&resid[4 * lane];

    int nodeL = t & 63;   // load-phase node
    int q     = t >> 6;   // load-phase dim quarter

    const int NT = (NN + 63) / 64;
    for (int tile = blockIdx.x; tile < NT; tile += gridDim.x) {
        __syncthreads();
        int gn = tile * 64 + nodeL;
        #pragma unroll
        for (int i = 0; i < 8; i++) {
            int k0 = 32 * q + 4 * i;
            float4 v = make_float4(0.f, 0.f, 0.f, 0.f);
            if (gn < NN) v = *(const float4*)&nfeat[(size_t)gn * D + k0];
            sNf[(k0 + 0) * 64 + nodeL] = v.x;
            sNf[(k0 + 1) * 64 + nodeL] = v.y;
            sNf[(k0 + 2) * 64 + nodeL] = v.z;
            sNf[(k0 + 3) * 64 + nodeL] = v.w;
        }
        __syncthreads();

        ull acc[8][2];
        #pragma unroll
        for (int j = 0; j < 8; j++) { acc[j][0] = b01; acc[j][1] = b23; }

        #pragma unroll 8
        for (int k = 0; k < 128; k++) {
            ulonglong2 wv = *(const ulonglong2*)&sW[k * 64 + 2 * lane];
            float4 f0 = *(const float4*)&sNf[k * 64 + 8 * w];
            float4 f1 = *(const float4*)&sNf[k * 64 + 8 * w + 4];
            float fv[8] = {f0.x, f0.y, f0.z, f0.w, f1.x, f1.y, f1.z, f1.w};
            #pragma unroll
            for (int j = 0; j < 8; j++) {
                ull dj = dup2(fv[j]);
                fma2(acc[j][0], dj, wv.x);
                fma2(acc[j][1], dj, wv.y);
            }
        }

        #pragma unroll
        for (int j = 0; j < 8; j++) {
            int n = tile * 64 + 8 * w + j;
            if (n >= NN) continue;
            float dv  = (float)g_deg[n] + 1.0f;
            float inv = 1.0f / dv;
            float nr  = rsqrtf(dv);
            float2 p0 = unpk(acc[j][0]), p1 = unpk(acc[j][1]);
            *(float4*)&g_g[(size_t)n * D + 4 * lane] =
                make_float4(nr * p0.x, nr * p0.y, nr * p1.x, nr * p1.y);
            *(float4*)&out[(size_t)n * D + 4 * lane] =
                make_float4((p0.x + r4.x) * inv, (p0.y + r4.y) * inv,
                            (p1.x + r4.z) * inv, (p1.y + r4.w) * inv);
            if (lane == 0) g_norm[n] = nr;
        }
    }
}

// ---------------- K3: gather-aggregate + fused We matvec + final out ----------------
__global__ __launch_bounds__(256) void k_agg(
    const float* __restrict__ efeat, const float* __restrict__ We,
    const float* __restrict__ be, float* __restrict__ out)
{
    extern __shared__ ull sma[];
    ull*   sWe = sma;                      // [64][64] u64 (We dim-pairs) = 32 KB
    float* sAe = (float*)(sma + 64 * 64);  // [8 warps][64] = 2 KB

    int t = threadIdx.x, lane = t & 31, w = t >> 5;

    const ulonglong2* We128 = (const ulonglong2*)We;
    ulonglong2* sWe2 = (ulonglong2*)sWe;
    for (int i = t; i < 64 * 64 / 2; i += 256) sWe2[i] = We128[i];
    __syncthreads();

    float4 be4 = *(const float4*)&be[4 * lane];

    int n = blockIdx.x * 8 + w;   // grid = 6250 blocks * 8 warps = 50000
    if (n >= NN) return;

    int deg  = g_deg[n];
    int dcap = deg < CAP ? deg : CAP;
    int base = n * CAP;

    ull ag0 = 0, ag1 = 0, ae = 0;
    float se = 0.f;

    for (int c0 = 0; c0 < dcap; c0 += 32) {
        int m = dcap - c0; if (m > 32) m = 32;
        int2 pe = make_int2(0, 0);
        if (lane < m) pe = g_perm[base + c0 + lane];
        for (int i = 0; i < m; i++) {
            int s = __shfl_sync(0xffffffffu, pe.x, i);
            int e = __shfl_sync(0xffffffffu, pe.y, i);
            float ns = g_norm[s];
            ulonglong2 gv = *(const ulonglong2*)&g_g[(size_t)s * D + 4 * lane];
            add2(ag0, gv.x);
            add2(ag1, gv.y);
            ull ev = *(const ull*)&efeat[(size_t)e * DE + 2 * lane];
            fma2(ae, ev, dup2(ns));
            se += ns;
        }
    }

    // share acc_e across the warp via smem
    *(ull*)&sAe[w * 64 + 2 * lane] = ae;
    __syncwarp();

    // matvec: mv[4l..4l+3] = sum_k acc_e[k] * We[k][4l..4l+3]
    ull mv0 = 0, mv1 = 0;
    #pragma unroll 8
    for (int k = 0; k < 64; k++) {
        float a = sAe[w * 64 + k];
        ull a2 = dup2(a);
        ulonglong2 wv = *(const ulonglong2*)&sWe[k * 64 + 2 * lane];
        fma2(mv0, a2, wv.x);
        fma2(mv1, a2, wv.y);
    }

    float nr = g_norm[n];
    float2 g0 = unpk(ag0), g1 = unpk(ag1);
    float2 m0 = unpk(mv0), m1 = unpk(mv1);
    float4 ov = *(const float4*)&out[(size_t)n * D + 4 * lane];
    ov.x += nr * (g0.x + m0.x + se * be4.x);
    ov.y += nr * (g0.y + m0.y + se * be4.y);
    ov.z += nr * (g1.x + m1.x + se * be4.z);
    ov.w += nr * (g1.y + m1.y + se * be4.w);
    *(float4*)&out[(size_t)n * D + 4 * lane] = ov;
}

// ---------------- K4: overflow fallback (expected count = 0) ----------------
__global__ void k_ovf(const float* __restrict__ efeat, const float* __restrict__ We,
                      const float* __restrict__ be, float* __restrict__ out)
{
    int cnt = g_novf; if (cnt > 1024) cnt = 1024;
    if (cnt <= 0) return;
    int lane = threadIdx.x & 31;
    int warp = (blockIdx.x * blockDim.x + threadIdx.x) >> 5;
    int nw   = (gridDim.x * blockDim.x) >> 5;
    float4 be4 = *(const float4*)&be[4 * lane];
    for (int o = warp; o < cnt; o += nw) {
        int4 v = g_ovf[o];
        int s = v.x, e = v.y, d = v.z;
        float ns = g_norm[s], nd = g_norm[d];
        float4 mv = make_float4(0.f, 0.f, 0.f, 0.f);
        for (int k = 0; k < DE; k++) {
            float a = efeat[(size_t)e * DE + k];
            float4 wv = *(const float4*)&We[(size_t)k * D + 4 * lane];
            mv.x += a * wv.x; mv.y += a * wv.y; mv.z += a * wv.z; mv.w += a * wv.w;
        }
        float4 gv = *(const float4*)&g_g[(size_t)s * D + 4 * lane];
        float4 c = make_float4(nd * (gv.x + ns * (mv.x + be4.x)),
                               nd * (gv.y + ns * (mv.y + be4.y)),
                               nd * (gv.z + ns * (mv.z + be4.z)),
                               nd * (gv.w + ns * (mv.w + be4.w)));
        red4(&out[(size_t)d * D + 4 * lane], c);
    }
}

// ---------------- launch ----------------
extern "C" void kernel_launch(void* const* d_in, const int* in_sizes, int n_in,
                              void* d_out, int out_size)
{
    const int*   src   = (const int*)  d_in[0];
    const int*   dst   = (const int*)  d_in[1];
    const float* nfeat = (const float*)d_in[2];
    const float* efeat = (const float*)d_in[3];
    const float* Wn    = (const float*)d_in[4];
    const float* bn    = (const float*)d_in[5];
    const float* We    = (const float*)d_in[6];
    const float* be    = (const float*)d_in[7];
    const float* resid = (const float*)d_in[8];
    float* out = (float*)d_out;

    const int SM_NODE = 128 * 64 * 8 + 128 * 64 * 4;  // 96 KB
    const int SM_AGG  = 64 * 64 * 8 + 8 * 64 * 4;     // 34 KB
    cudaFuncSetAttribute(k_node, cudaFuncAttributeMaxDynamicSharedMemorySize, SM_NODE);
    cudaFuncSetAttribute(k_agg,  cudaFuncAttributeMaxDynamicSharedMemorySize, SM_AGG);

    k_zero <<<64, 256>>>();
    k_build<<<(NE + 255) / 256, 256>>>(src, dst);
    k_node <<<782, 256, SM_NODE>>>(nfeat, Wn, bn, resid, out);
    k_agg  <<<6250, 256, SM_AGG>>>(efeat, We, be, out);
    k_ovf  <<<8, 256>>>(efeat, We, be, out);
}

// round 4
// speedup vs baseline: 1.2734x; 1.0208x over previous
#include <cuda_runtime.h>

#define NN 50000
#define NE 800000
#define D  128
#define DE 64
#define CAP 80

typedef unsigned long long ull;

// ---------------- device scratch (no allocs allowed) ----------------
__device__ __align__(16) int   g_deg [NN];
__device__ __align__(16) float g_norm[NN];
__device__ __align__(16) float g_g   [NN * D];     // norm[n] * (nfeat@Wn + bn)
__device__ __align__(16) int2  g_perm[NN * CAP];   // per-dst edge list {src, e}
__device__ __align__(16) int4  g_ovf [1024];       // overflow {src, e, dst, 0}
__device__ int g_novf;

// ---------------- PTX helpers ----------------
__device__ __forceinline__ void fma2(ull &d, ull a, ull b) {
    asm("fma.rn.f32x2 %0, %1, %2, %0;" : "+l"(d) : "l"(a), "l"(b));
}
__device__ __forceinline__ void add2(ull &d, ull a) {
    asm("add.rn.f32x2 %0, %0, %1;" : "+l"(d) : "l"(a));
}
__device__ __forceinline__ ull dup2(float x) {
    ull r; asm("mov.b64 %0, {%1, %1};" : "=l"(r) : "f"(x)); return r;
}
__device__ __forceinline__ ull pack2(float a, float b) {
    ull r; asm("mov.b64 %0, {%1, %2};" : "=l"(r) : "f"(a), "f"(b)); return r;
}
__device__ __forceinline__ float2 unpk(ull v) {
    float2 r; asm("mov.b64 {%0, %1}, %2;" : "=f"(r.x), "=f"(r.y) : "l"(v)); return r;
}
__device__ __forceinline__ void red4(float* p, float4 v) {
    asm volatile("red.global.add.v4.f32 [%0], {%1, %2, %3, %4};"
                 :: "l"(p), "f"(v.x), "f"(v.y), "f"(v.z), "f"(v.w) : "memory");
}
__device__ __forceinline__ ulonglong2 ldg2(const ull* p) {
    ulonglong2 r;
    asm("ld.global.nc.v2.u64 {%0, %1}, [%2];" : "=l"(r.x), "=l"(r.y) : "l"(p));
    return r;
}
__device__ __forceinline__ ull ldg1(const ull* p) {
    ull r; asm("ld.global.nc.u64 %0, [%1];" : "=l"(r) : "l"(p)); return r;
}
__device__ __forceinline__ float ldgf(const float* p) {
    float r; asm("ld.global.nc.f32 %0, [%1];" : "=f"(r) : "l"(p)); return r;
}

// ---------------- K0: zero counters ----------------
__global__ void k_zero() {
    int i = blockIdx.x * blockDim.x + threadIdx.x;
    int st = gridDim.x * blockDim.x;
    for (int j = i; j < NN; j += st) g_deg[j] = 0;
    if (i == 0) g_novf = 0;
}

// ---------------- K1: build per-dst buckets + degree ----------------
__global__ void k_build(const int* __restrict__ src, const int* __restrict__ dst) {
    int e = blockIdx.x * blockDim.x + threadIdx.x;
    if (e >= NE) return;
    int d = dst[e], s = src[e];
    int c = atomicAdd(&g_deg[d], 1);
    if (c < CAP) {
        g_perm[d * CAP + c] = make_int2(s, e);
    } else {
        int o = atomicAdd(&g_novf, 1);
        if (o < 1024) g_ovf[o] = make_int4(s, e, d, 0);
    }
}

// ---------------- K2: node GEMM  g = norm*(nfeat@Wn+bn);  out = (h+resid)/deg ----------------
__global__ __launch_bounds__(256) void k_node(
    const float* __restrict__ nfeat, const float* __restrict__ Wn,
    const float* __restrict__ bn, const float* __restrict__ resid,
    float* __restrict__ out)
{
    extern __shared__ ull smn[];
    ull*   sW  = smn;                       // [128][64] u64 (Wn dim-pairs) = 64 KB
    float* sNf = (float*)(smn + 128 * 64);  // [k][node] = 32 KB

    int t = threadIdx.x, lane = t & 31, w = t >> 5;

    const ulonglong2* Wn128 = (const ulonglong2*)Wn;
    ulonglong2* sW2 = (ulonglong2*)sW;
    for (int i = t; i < 128 * 64 / 2; i += 256) sW2[i] = Wn128[i];

    float4 bnv = *(const float4*)&bn[4 * lane];
    ull b01 = pack2(bnv.x, bnv.y), b23 = pack2(bnv.z, bnv.w);
    float4 r4 = *(const float4*)&resid[4 * lane];

    int nodeL = t & 63;   // load-phase node
    int q     = t >> 6;   // load-phase dim quarter

    const int NT = (NN + 63) / 64;
    for (int tile = blockIdx.x; tile < NT; tile += gridDim.x) {
        __syncthreads();
        int gn = tile * 64 + nodeL;
        #pragma unroll
        for (int i = 0; i < 8; i++) {
            int k0 = 32 * q + 4 * i;
            float4 v = make_float4(0.f, 0.f, 0.f, 0.f);
            if (gn < NN) v = *(const float4*)&nfeat[(size_t)gn * D + k0];
            sNf[(k0 + 0) * 64 + nodeL] = v.x;
            sNf[(k0 + 1) * 64 + nodeL] = v.y;
            sNf[(k0 + 2) * 64 + nodeL] = v.z;
            sNf[(k0 + 3) * 64 + nodeL] = v.w;
        }
        __syncthreads();

        ull acc[8][2];
        #pragma unroll
        for (int j = 0; j < 8; j++) { acc[j][0] = b01; acc[j][1] = b23; }

        #pragma unroll 8
        for (int k = 0; k < 128; k++) {
            ulonglong2 wv = *(const ulonglong2*)&sW[k * 64 + 2 * lane];
            float4 f0 = *(const float4*)&sNf[k * 64 + 8 * w];
            float4 f1 = *(const float4*)&sNf[k * 64 + 8 * w + 4];
            float fv[8] = {f0.x, f0.y, f0.z, f0.w, f1.x, f1.y, f1.z, f1.w};
            #pragma unroll
            for (int j = 0; j < 8; j++) {
                ull dj = dup2(fv[j]);
                fma2(acc[j][0], dj, wv.x);
                fma2(acc[j][1], dj, wv.y);
            }
        }

        #pragma unroll
        for (int j = 0; j < 8; j++) {
            int n = tile * 64 + 8 * w + j;
            if (n >= NN) continue;
            float dv  = (float)g_deg[n] + 1.0f;
            float inv = 1.0f / dv;
            float nr  = rsqrtf(dv);
            float2 p0 = unpk(acc[j][0]), p1 = unpk(acc[j][1]);
            *(float4*)&g_g[(size_t)n * D + 4 * lane] =
                make_float4(nr * p0.x, nr * p0.y, nr * p1.x, nr * p1.y);
            *(float4*)&out[(size_t)n * D + 4 * lane] =
                make_float4((p0.x + r4.x) * inv, (p0.y + r4.y) * inv,
                            (p1.x + r4.z) * inv, (p1.y + r4.w) * inv);
            if (lane == 0) g_norm[n] = nr;
        }
    }
}

// ---------------- K3: gather-aggregate (4-edge batched) + fused We matvec ----------------
__global__ __launch_bounds__(256) void k_agg(
    const float* __restrict__ efeat, const float* __restrict__ We,
    const float* __restrict__ be, float* __restrict__ out)
{
    extern __shared__ ull sma[];
    ull*   sWe = sma;                      // [64][64] u64 (We dim-pairs) = 32 KB
    float* sAe = (float*)(sma + 64 * 64);  // [8 warps][64] = 2 KB

    int t = threadIdx.x, lane = t & 31, w = t >> 5;

    const ulonglong2* We128 = (const ulonglong2*)We;
    ulonglong2* sWe2 = (ulonglong2*)sWe;
    for (int i = t; i < 64 * 64 / 2; i += 256) sWe2[i] = We128[i];
    __syncthreads();

    float4 be4 = *(const float4*)&be[4 * lane];

    int n = blockIdx.x * 8 + w;   // grid = 6250 blocks * 8 warps = 50000
    if (n >= NN) return;

    int deg  = g_deg[n];
    int dcap = deg < CAP ? deg : CAP;
    int base = n * CAP;

    ull ag0 = 0, ag1 = 0, ae = 0;
    float se = 0.f;
    const int go = 4 * lane;   // g_g element offset for this lane
    const int eo = 2 * lane;   // efeat element offset for this lane

    for (int c0 = 0; c0 < dcap; c0 += 32) {
        int m = dcap - c0; if (m > 32) m = 32;
        int2 pe = make_int2(0, 0);
        if (lane < m) pe = g_perm[base + c0 + lane];

        int i = 0;
        for (; i + 4 <= m; i += 4) {
            int s0 = __shfl_sync(0xffffffffu, pe.x, i + 0);
            int e0 = __shfl_sync(0xffffffffu, pe.y, i + 0);
            int s1 = __shfl_sync(0xffffffffu, pe.x, i + 1);
            int e1 = __shfl_sync(0xffffffffu, pe.y, i + 1);
            int s2 = __shfl_sync(0xffffffffu, pe.x, i + 2);
            int e2 = __shfl_sync(0xffffffffu, pe.y, i + 2);
            int s3 = __shfl_sync(0xffffffffu, pe.x, i + 3);
            int e3 = __shfl_sync(0xffffffffu, pe.y, i + 3);

            float ns0 = ldgf(&g_norm[s0]);
            float ns1 = ldgf(&g_norm[s1]);
            float ns2 = ldgf(&g_norm[s2]);
            float ns3 = ldgf(&g_norm[s3]);
            ulonglong2 gv0 = ldg2((const ull*)&g_g[(size_t)s0 * D + go]);
            ulonglong2 gv1 = ldg2((const ull*)&g_g[(size_t)s1 * D + go]);
            ulonglong2 gv2 = ldg2((const ull*)&g_g[(size_t)s2 * D + go]);
            ulonglong2 gv3 = ldg2((const ull*)&g_g[(size_t)s3 * D + go]);
            ull ev0 = ldg1((const ull*)&efeat[(size_t)e0 * DE + eo]);
            ull ev1 = ldg1((const ull*)&efeat[(size_t)e1 * DE + eo]);
            ull ev2 = ldg1((const ull*)&efeat[(size_t)e2 * DE + eo]);
            ull ev3 = ldg1((const ull*)&efeat[(size_t)e3 * DE + eo]);

            add2(ag0, gv0.x); add2(ag1, gv0.y);
            add2(ag0, gv1.x); add2(ag1, gv1.y);
            add2(ag0, gv2.x); add2(ag1, gv2.y);
            add2(ag0, gv3.x); add2(ag1, gv3.y);
            fma2(ae, ev0, dup2(ns0));
            fma2(ae, ev1, dup2(ns1));
            fma2(ae, ev2, dup2(ns2));
            fma2(ae, ev3, dup2(ns3));
            se += (ns0 + ns1) + (ns2 + ns3);
        }
        for (; i < m; i++) {
            int s = __shfl_sync(0xffffffffu, pe.x, i);
            int e = __shfl_sync(0xffffffffu, pe.y, i);
            float ns = ldgf(&g_norm[s]);
            ulonglong2 gv = ldg2((const ull*)&g_g[(size_t)s * D + go]);
            ull ev = ldg1((const ull*)&efeat[(size_t)e * DE + eo]);
            add2(ag0, gv.x);
            add2(ag1, gv.y);
            fma2(ae, ev, dup2(ns));
            se += ns;
        }
    }

    // share acc_e across the warp via smem
    *(ull*)&sAe[w * 64 + 2 * lane] = ae;
    __syncwarp();

    // matvec: mv[4l..4l+3] = sum_k acc_e[k] * We[k][4l..4l+3]
    ull mv0 = 0, mv1 = 0;
    #pragma unroll 8
    for (int k = 0; k < 64; k++) {
        float a = sAe[w * 64 + k];
        ull a2 = dup2(a);
        ulonglong2 wv = *(const ulonglong2*)&sWe[k * 64 + 2 * lane];
        fma2(mv0, a2, wv.x);
        fma2(mv1, a2, wv.y);
    }

    float nr = g_norm[n];
    float2 g0 = unpk(ag0), g1 = unpk(ag1);
    float2 m0 = unpk(mv0), m1 = unpk(mv1);
    float4 ov = *(const float4*)&out[(size_t)n * D + 4 * lane];
    ov.x += nr * (g0.x + m0.x + se * be4.x);
    ov.y += nr * (g0.y + m0.y + se * be4.y);
    ov.z += nr * (g1.x + m1.x + se * be4.z);
    ov.w += nr * (g1.y + m1.y + se * be4.w);
    *(float4*)&out[(size_t)n * D + 4 * lane] = ov;
}

// ---------------- K4: overflow fallback (expected count = 0) ----------------
__global__ void k_ovf(const float* __restrict__ efeat, const float* __restrict__ We,
                      const float* __restrict__ be, float* __restrict__ out)
{
    int cnt = g_novf; if (cnt > 1024) cnt = 1024;
    if (cnt <= 0) return;
    int lane = threadIdx.x & 31;
    int warp = (blockIdx.x * blockDim.x + threadIdx.x) >> 5;
    int nw   = (gridDim.x * blockDim.x) >> 5;
    float4 be4 = *(const float4*)&be[4 * lane];
    for (int o = warp; o < cnt; o += nw) {
        int4 v = g_ovf[o];
        int s = v.x, e = v.y, d = v.z;
        float ns = g_norm[s], nd = g_norm[d];
        float4 mv = make_float4(0.f, 0.f, 0.f, 0.f);
        for (int k = 0; k < DE; k++) {
            float a = efeat[(size_t)e * DE + k];
            float4 wv = *(const float4*)&We[(size_t)k * D + 4 * lane];
            mv.x += a * wv.x; mv.y += a * wv.y; mv.z += a * wv.z; mv.w += a * wv.w;
        }
        float4 gv = *(const float4*)&g_g[(size_t)s * D + 4 * lane];
        float4 c = make_float4(nd * (gv.x + ns * (mv.x + be4.x)),
                               nd * (gv.y + ns * (mv.y + be4.y)),
                               nd * (gv.z + ns * (mv.z + be4.z)),
                               nd * (gv.w + ns * (mv.w + be4.w)));
        red4(&out[(size_t)d * D + 4 * lane], c);
    }
}

// ---------------- launch ----------------
extern "C" void kernel_launch(void* const* d_in, const int* in_sizes, int n_in,
                              void* d_out, int out_size)
{
    const int*   src   = (const int*)  d_in[0];
    const int*   dst   = (const int*)  d_in[1];
    const float* nfeat = (const float*)d_in[2];
    const float* efeat = (const float*)d_in[3];
    const float* Wn    = (const float*)d_in[4];
    const float* bn    = (const float*)d_in[5];
    const float* We    = (const float*)d_in[6];
    const float* be    = (const float*)d_in[7];
    const float* resid = (const float*)d_in[8];
    float* out = (float*)d_out;

    const int SM_NODE = 128 * 64 * 8 + 128 * 64 * 4;  // 96 KB
    const int SM_AGG  = 64 * 64 * 8 + 8 * 64 * 4;     // 34 KB
    cudaFuncSetAttribute(k_node, cudaFuncAttributeMaxDynamicSharedMemorySize, SM_NODE);
    cudaFuncSetAttribute(k_agg,  cudaFuncAttributeMaxDynamicSharedMemorySize, SM_AGG);

    k_zero <<<64, 256>>>();
    k_build<<<(NE + 255) / 256, 256>>>(src, dst);
    k_node <<<782, 256, SM_NODE>>>(nfeat, Wn, bn, resid, out);
    k_agg  <<<6250, 256, SM_AGG>>>(efeat, We, be, out);
    k_ovf  <<<8, 256>>>(efeat, We, be, out);
}